// round 1
// baseline (speedup 1.0000x reference)
#include <cuda_runtime.h>
#include <math.h>

#define NTOK  8192
#define INDIM 1024
#define CDIM  512

// Scratch (allocation-free rule: __device__ globals)
__device__ float g_K[NTOK * CDIM];
__device__ float g_V[NTOK * CDIM];
__device__ float g_Q[NTOK * CDIM];
__device__ float g_rowsum[NTOK];

// ---------------------------------------------------------------------------
__global__ void zero_rowsum_kernel() {
    int i = blockIdx.x * blockDim.x + threadIdx.x;
    if (i < NTOK) g_rowsum[i] = 0.0f;
}

// ---------------------------------------------------------------------------
// Projection: out = concat(u,z) @ W^T + b.  M=8192, N=512, K=1024.
// sel: 0 -> g_K, 1 -> g_V, 2 -> g_Q
__global__ __launch_bounds__(256) void proj_kernel(
    const float* __restrict__ u, const float* __restrict__ z,
    const float* __restrict__ W, const float* __restrict__ bias, int sel)
{
    constexpr int BM = 128, BN = 128, BK = 16, PAD = 4;
    __shared__ float As[BK][BM + PAD];
    __shared__ float Bs[BK][BN + PAD];

    float* out = (sel == 0) ? g_K : (sel == 1) ? g_V : g_Q;

    const int bm = blockIdx.y * BM;
    const int bn = blockIdx.x * BN;
    const int tid = threadIdx.x;
    const int tx = tid & 15, ty = tid >> 4;

    float acc[8][8];
#pragma unroll
    for (int i = 0; i < 8; i++)
#pragma unroll
        for (int j = 0; j < 8; j++) acc[i][j] = 0.0f;

    for (int kt = 0; kt < INDIM; kt += BK) {
        // concat(u,z): each BK tile lies entirely in u (kt<512) or z
        const float* A = (kt < 512) ? u : z;
        const int kb = (kt < 512) ? kt : kt - 512;
#pragma unroll
        for (int l = 0; l < 2; l++) {
            int f = tid + l * 256;
            int r = f >> 2;
            int c4 = (f & 3) << 2;
            float4 va = *(const float4*)(A + (size_t)(bm + r) * 512 + kb + c4);
            As[c4 + 0][r] = va.x; As[c4 + 1][r] = va.y;
            As[c4 + 2][r] = va.z; As[c4 + 3][r] = va.w;
            float4 vb = *(const float4*)(W + (size_t)(bn + r) * INDIM + kt + c4);
            Bs[c4 + 0][r] = vb.x; Bs[c4 + 1][r] = vb.y;
            Bs[c4 + 2][r] = vb.z; Bs[c4 + 3][r] = vb.w;
        }
        __syncthreads();
#pragma unroll
        for (int k = 0; k < BK; k++) {
            float a[8], b[8];
            *(float4*)&a[0] = *(const float4*)&As[k][ty * 8];
            *(float4*)&a[4] = *(const float4*)&As[k][ty * 8 + 4];
            *(float4*)&b[0] = *(const float4*)&Bs[k][tx * 8];
            *(float4*)&b[4] = *(const float4*)&Bs[k][tx * 8 + 4];
#pragma unroll
            for (int i = 0; i < 8; i++)
#pragma unroll
                for (int j = 0; j < 8; j++) acc[i][j] = fmaf(a[i], b[j], acc[i][j]);
        }
        __syncthreads();
    }

#pragma unroll
    for (int i = 0; i < 8; i++) {
        int gr = bm + ty * 8 + i;
#pragma unroll
        for (int j = 0; j < 8; j += 4) {
            int gc = bn + tx * 8 + j;
            float4 o;
            o.x = acc[i][j + 0] + bias[gc + 0];
            o.y = acc[i][j + 1] + bias[gc + 1];
            o.z = acc[i][j + 2] + bias[gc + 2];
            o.w = acc[i][j + 3] + bias[gc + 3];
            *(float4*)(out + (size_t)gr * CDIM + gc) = o;
        }
    }
}

// ---------------------------------------------------------------------------
// Scores: attn[m,n] = exp(Q[m]·K[n] / sqrt(512)), diagonal -> 0.
// Accumulates g_rowsum via shared + global atomics. attn left UNNORMALIZED.
__global__ __launch_bounds__(256) void scores_kernel(float* __restrict__ attn)
{
    constexpr int BM = 128, BN = 128, BK = 16, PAD = 4;
    __shared__ float As[BK][BM + PAD];
    __shared__ float Bs[BK][BN + PAD];
    __shared__ float rsum[BM];

    const int bm = blockIdx.y * BM;
    const int bn = blockIdx.x * BN;
    const int tid = threadIdx.x;
    const int tx = tid & 15, ty = tid >> 4;

    if (tid < BM) rsum[tid] = 0.0f;

    float acc[8][8];
#pragma unroll
    for (int i = 0; i < 8; i++)
#pragma unroll
        for (int j = 0; j < 8; j++) acc[i][j] = 0.0f;

    for (int kt = 0; kt < CDIM; kt += BK) {
#pragma unroll
        for (int l = 0; l < 2; l++) {
            int f = tid + l * 256;
            int r = f >> 2;
            int c4 = (f & 3) << 2;
            float4 va = *(const float4*)(g_Q + (size_t)(bm + r) * CDIM + kt + c4);
            As[c4 + 0][r] = va.x; As[c4 + 1][r] = va.y;
            As[c4 + 2][r] = va.z; As[c4 + 3][r] = va.w;
            float4 vb = *(const float4*)(g_K + (size_t)(bn + r) * CDIM + kt + c4);
            Bs[c4 + 0][r] = vb.x; Bs[c4 + 1][r] = vb.y;
            Bs[c4 + 2][r] = vb.z; Bs[c4 + 3][r] = vb.w;
        }
        __syncthreads();
#pragma unroll
        for (int k = 0; k < BK; k++) {
            float a[8], b[8];
            *(float4*)&a[0] = *(const float4*)&As[k][ty * 8];
            *(float4*)&a[4] = *(const float4*)&As[k][ty * 8 + 4];
            *(float4*)&b[0] = *(const float4*)&Bs[k][tx * 8];
            *(float4*)&b[4] = *(const float4*)&Bs[k][tx * 8 + 4];
#pragma unroll
            for (int i = 0; i < 8; i++)
#pragma unroll
                for (int j = 0; j < 8; j++) acc[i][j] = fmaf(a[i], b[j], acc[i][j]);
        }
        __syncthreads();
    }

    const float scale = 0.044194173824159216f;  // 1/sqrt(512)
    float rp[8];
#pragma unroll
    for (int i = 0; i < 8; i++) rp[i] = 0.0f;

#pragma unroll
    for (int i = 0; i < 8; i++) {
        int gr = bm + ty * 8 + i;
        float e[8];
#pragma unroll
        for (int j = 0; j < 8; j++) {
            int gc = bn + tx * 8 + j;
            float v = (gr == gc) ? 0.0f : expf(acc[i][j] * scale);
            e[j] = v;
            rp[i] += v;
        }
        float* dst = attn + (size_t)gr * NTOK + bn + tx * 8;
        *(float4*)(dst + 0) = make_float4(e[0], e[1], e[2], e[3]);
        *(float4*)(dst + 4) = make_float4(e[4], e[5], e[6], e[7]);
    }

#pragma unroll
    for (int i = 0; i < 8; i++) atomicAdd(&rsum[ty * 8 + i], rp[i]);
    __syncthreads();
    if (tid < BM) atomicAdd(&g_rowsum[bm + tid], rsum[tid]);
}

// ---------------------------------------------------------------------------
// AV: m_bar = (attn_unnormalized @ V) * (1/rowsum) per row.
__global__ __launch_bounds__(256) void av_kernel(
    const float* __restrict__ attn, float* __restrict__ m_out)
{
    constexpr int BM = 128, BN = 128, BK = 16, PAD = 4;
    __shared__ float As[BK][BM + PAD];
    __shared__ float Bs[BK][BN + PAD];

    const int bm = blockIdx.y * BM;
    const int bn = blockIdx.x * BN;
    const int tid = threadIdx.x;
    const int tx = tid & 15, ty = tid >> 4;

    float acc[8][8];
#pragma unroll
    for (int i = 0; i < 8; i++)
#pragma unroll
        for (int j = 0; j < 8; j++) acc[i][j] = 0.0f;

    for (int kt = 0; kt < NTOK; kt += BK) {
        // A tile: attn rows bm..bm+127, cols kt..kt+15
#pragma unroll
        for (int l = 0; l < 2; l++) {
            int f = tid + l * 256;
            int r = f >> 2;
            int c4 = (f & 3) << 2;
            float4 va = *(const float4*)(attn + (size_t)(bm + r) * NTOK + kt + c4);
            As[c4 + 0][r] = va.x; As[c4 + 1][r] = va.y;
            As[c4 + 2][r] = va.z; As[c4 + 3][r] = va.w;
            // B tile: V rows kt..kt+15, cols bn..bn+127 (row-major, direct)
            int r2 = f >> 5;            // 0..15
            int c4b = (f & 31) << 2;    // 0..124
            float4 vb = *(const float4*)(g_V + (size_t)(kt + r2) * CDIM + bn + c4b);
            *(float4*)&Bs[r2][c4b] = vb;
        }
        __syncthreads();
#pragma unroll
        for (int k = 0; k < BK; k++) {
            float a[8], b[8];
            *(float4*)&a[0] = *(const float4*)&As[k][ty * 8];
            *(float4*)&a[4] = *(const float4*)&As[k][ty * 8 + 4];
            *(float4*)&b[0] = *(const float4*)&Bs[k][tx * 8];
            *(float4*)&b[4] = *(const float4*)&Bs[k][tx * 8 + 4];
#pragma unroll
            for (int i = 0; i < 8; i++)
#pragma unroll
                for (int j = 0; j < 8; j++) acc[i][j] = fmaf(a[i], b[j], acc[i][j]);
        }
        __syncthreads();
    }

#pragma unroll
    for (int i = 0; i < 8; i++) {
        int gr = bm + ty * 8 + i;
        float inv = 1.0f / g_rowsum[gr];
#pragma unroll
        for (int j = 0; j < 8; j += 4) {
            int gc = bn + tx * 8 + j;
            float4 o;
            o.x = acc[i][j + 0] * inv;
            o.y = acc[i][j + 1] * inv;
            o.z = acc[i][j + 2] * inv;
            o.w = acc[i][j + 3] * inv;
            *(float4*)(m_out + (size_t)gr * CDIM + gc) = o;
        }
    }
}

// ---------------------------------------------------------------------------
// Normalize attn in place: attn[i,j] *= 1/rowsum[i].
__global__ __launch_bounds__(256) void normalize_kernel(float* __restrict__ attn)
{
    size_t q = (size_t)blockIdx.x * blockDim.x + threadIdx.x;  // float4 index
    size_t row = q >> 11;                                      // (4q)/8192
    float inv = 1.0f / g_rowsum[row];
    float4 v = ((float4*)attn)[q];
    v.x *= inv; v.y *= inv; v.z *= inv; v.w *= inv;
    ((float4*)attn)[q] = v;
}

// ---------------------------------------------------------------------------
extern "C" void kernel_launch(void* const* d_in, const int* in_sizes, int n_in,
                              void* d_out, int out_size)
{
    (void)in_sizes; (void)n_in; (void)out_size;
    const float* u  = (const float*)d_in[0];
    const float* z  = (const float*)d_in[1];
    const float* Wk = (const float*)d_in[2];
    const float* bk = (const float*)d_in[3];
    const float* Wv = (const float*)d_in[4];
    const float* bv = (const float*)d_in[5];
    const float* Wq = (const float*)d_in[6];
    const float* bq = (const float*)d_in[7];

    float* m_out    = (float*)d_out;                       // (8192, 512)
    float* attn_out = m_out + (size_t)NTOK * CDIM;         // (8192, 8192)

    zero_rowsum_kernel<<<NTOK / 256, 256>>>();

    dim3 pgrid(CDIM / 128, NTOK / 128);                    // (4, 64)
    proj_kernel<<<pgrid, 256>>>(u, z, Wk, bk, 0);
    proj_kernel<<<pgrid, 256>>>(u, z, Wv, bv, 1);
    proj_kernel<<<pgrid, 256>>>(u, z, Wq, bq, 2);

    dim3 sgrid(NTOK / 128, NTOK / 128);                    // (64, 64)
    scores_kernel<<<sgrid, 256>>>(attn_out);

    dim3 agrid(CDIM / 128, NTOK / 128);                    // (4, 64)
    av_kernel<<<agrid, 256>>>(attn_out, m_out);

    size_t nq = ((size_t)NTOK * NTOK) / 4;                 // 16,777,216 float4
    normalize_kernel<<<(unsigned)(nq / 256), 256>>>(attn_out);
}

// round 4
// speedup vs baseline: 2.4167x; 2.4167x over previous
#include <cuda_runtime.h>
#include <cuda_bf16.h>
#include <cstdint>

#define NTOK  8192
#define INDIM 1024
#define CDIM  512

using bf16 = __nv_bfloat16;

// ---------------------------------------------------------------------------
// Scratch (__device__ globals; allocation-free rule)
__device__ __align__(16) bf16 g_Shi[NTOK * INDIM], g_Slo[NTOK * INDIM];     // concat(u,z) split
__device__ __align__(16) bf16 g_Whi[3][CDIM * INDIM], g_Wlo[3][CDIM * INDIM];
__device__ __align__(16) bf16 g_Khi[NTOK * CDIM], g_Klo[NTOK * CDIM];
__device__ __align__(16) bf16 g_Qhi[NTOK * CDIM], g_Qlo[NTOK * CDIM];
__device__ __align__(16) bf16 g_Vthi[CDIM * NTOK], g_Vtlo[CDIM * NTOK];     // V^T
__device__ __align__(16) bf16 g_Phi[(size_t)NTOK * NTOK], g_Plo[(size_t)NTOK * NTOK];
__device__ float g_rowsum[NTOK];

// ---------------------------------------------------------------------------
__device__ __forceinline__ uint32_t su32(const void* p) {
    uint32_t a;
    asm("{ .reg .u64 t; cvta.to.shared.u64 t, %1; cvt.u32.u64 %0, t; }" : "=r"(a) : "l"(p));
    return a;
}
__device__ __forceinline__ void cpa(uint32_t s, const void* g) {
    asm volatile("cp.async.cg.shared.global [%0], [%1], 16;"
                 :: "r"(s), "l"(__cvta_generic_to_global(g)));
}
#define CP_COMMIT asm volatile("cp.async.commit_group;" ::: "memory")
#define CP_WAIT1  asm volatile("cp.async.wait_group 1;" ::: "memory")
#define CP_WAIT0  asm volatile("cp.async.wait_group 0;" ::: "memory")

__device__ __forceinline__ void ldm4(uint32_t& r0, uint32_t& r1, uint32_t& r2, uint32_t& r3, uint32_t a) {
    asm volatile("ldmatrix.sync.aligned.m8n8.x4.shared.b16 {%0,%1,%2,%3}, [%4];"
                 : "=r"(r0), "=r"(r1), "=r"(r2), "=r"(r3) : "r"(a));
}
__device__ __forceinline__ void mma16816(float* c, const uint32_t* a, const uint32_t* b) {
    asm volatile(
        "mma.sync.aligned.m16n8k16.row.col.f32.bf16.bf16.f32 "
        "{%0,%1,%2,%3}, {%4,%5,%6,%7}, {%8,%9}, {%0,%1,%2,%3};"
        : "+f"(c[0]), "+f"(c[1]), "+f"(c[2]), "+f"(c[3])
        : "r"(a[0]), "r"(a[1]), "r"(a[2]), "r"(a[3]), "r"(b[0]), "r"(b[1]));
}
__device__ __forceinline__ void split2(float v, bf16& h, bf16& l) {
    h = __float2bfloat16(v);
    l = __float2bfloat16(v - __bfloat162float(h));
}
__device__ __forceinline__ uint32_t packbf(bf16 a, bf16 b) {
    return ((uint32_t)__bfloat16_as_ushort(b) << 16) | __bfloat16_as_ushort(a);
}

// ---------------------------------------------------------------------------
// SMEM: per stage: Ahi[128][80B] Alo Bhi Blo -> 40960B; 2 stages; +512 rsum
#define A_HI   0
#define A_LO   10240
#define B_HI   20480
#define B_LO   30720
#define STAGE  40960
#define SM_RSUM 81920
#define SM_TOTAL 82432

// Load one stage: A tile 128x32 (hi/lo) + B tile 128x32 (hi/lo)
__device__ __forceinline__ void load_stage(uint32_t sb,
    const bf16* __restrict__ Ah, const bf16* __restrict__ Al, int arow0, int64_t astr,
    const bf16* __restrict__ Bh, const bf16* __restrict__ Bl, int brow0, int64_t bstr,
    int k0, int tid)
{
#pragma unroll
    for (int i = 0; i < 2; i++) {
        int idx = tid + i * 256;
        int r = idx >> 2, c = idx & 3;
        uint32_t so = sb + r * 80 + c * 16;
        int64_t ga = (int64_t)(arow0 + r) * astr + k0 + c * 8;
        cpa(so + A_HI, Ah + ga);
        cpa(so + A_LO, Al + ga);
        int64_t gb = (int64_t)(brow0 + r) * bstr + k0 + c * 8;
        cpa(so + B_HI, Bh + gb);
        cpa(so + B_LO, Bl + gb);
    }
}

// Compute one 32-K chunk with x3 split combos into acc[4][4][4]
__device__ __forceinline__ void compute_stage(uint32_t sb, int wm, int wn, int lane,
                                              float acc[4][4][4])
{
    const uint32_t a_off = (lane & 15) * 80 + (lane >> 4) * 16;
    const uint32_t b_off = ((lane & 7) + ((lane >> 4) & 1) * 8) * 80 + ((lane >> 3) & 1) * 16;
#pragma unroll
    for (int kk = 0; kk < 2; kk++) {
        uint32_t bh[8], bl[8], a[16];
#pragma unroll
        for (int jj = 0; jj < 2; jj++) {
            uint32_t ad = sb + B_HI + (wn * 32 + jj * 16) * 80 + kk * 32 + b_off;
            ldm4(bh[jj * 4], bh[jj * 4 + 1], bh[jj * 4 + 2], bh[jj * 4 + 3], ad);
            ldm4(bl[jj * 4], bl[jj * 4 + 1], bl[jj * 4 + 2], bl[jj * 4 + 3], ad + (B_LO - B_HI));
        }
        // A hi: combos hi*hi, hi*lo
#pragma unroll
        for (int i = 0; i < 4; i++) {
            uint32_t ad = sb + A_HI + (wm * 64 + i * 16) * 80 + kk * 32 + a_off;
            ldm4(a[i * 4], a[i * 4 + 1], a[i * 4 + 2], a[i * 4 + 3], ad);
        }
#pragma unroll
        for (int i = 0; i < 4; i++)
#pragma unroll
            for (int j = 0; j < 4; j++) {
                mma16816(acc[i][j], &a[i * 4], &bh[j * 2]);
                mma16816(acc[i][j], &a[i * 4], &bl[j * 2]);
            }
        // A lo: combo lo*hi
#pragma unroll
        for (int i = 0; i < 4; i++) {
            uint32_t ad = sb + A_LO + (wm * 64 + i * 16) * 80 + kk * 32 + a_off;
            ldm4(a[i * 4], a[i * 4 + 1], a[i * 4 + 2], a[i * 4 + 3], ad);
        }
#pragma unroll
        for (int i = 0; i < 4; i++)
#pragma unroll
            for (int j = 0; j < 4; j++)
                mma16816(acc[i][j], &a[i * 4], &bh[j * 2]);
    }
}

#define GEMM_MAINLOOP(Ah, Al, astr, arow0, Bh, Bl, bstr, brow0, NCH)                        \
    load_stage(sb, Ah, Al, arow0, astr, Bh, Bl, brow0, bstr, 0, tid);                       \
    CP_COMMIT;                                                                              \
    for (int kc = 0; kc < (NCH); kc++) {                                                    \
        if (kc + 1 < (NCH)) {                                                               \
            load_stage(sb + ((kc + 1) & 1) * STAGE, Ah, Al, arow0, astr,                    \
                       Bh, Bl, brow0, bstr, (kc + 1) * 32, tid);                            \
            CP_COMMIT; CP_WAIT1;                                                            \
        } else { CP_WAIT0; }                                                                \
        __syncthreads();                                                                    \
        compute_stage(sb + (kc & 1) * STAGE, wm, wn, lane, acc);                            \
        __syncthreads();                                                                    \
    }

#define GEMM_PROLOG                                                   \
    extern __shared__ char smem[];                                    \
    const uint32_t sb = su32(smem);                                   \
    const int tid = threadIdx.x;                                      \
    const int lane = tid & 31, warp = tid >> 5;                       \
    const int wm = warp >> 2, wn = warp & 3;                          \
    float acc[4][4][4];                                               \
    _Pragma("unroll") for (int i = 0; i < 4; i++)                     \
    _Pragma("unroll") for (int j = 0; j < 4; j++)                     \
    _Pragma("unroll") for (int k = 0; k < 4; k++) acc[i][j][k] = 0.0f;

// ---------------------------------------------------------------------------
__global__ void zero_rowsum_kernel() {
    int i = blockIdx.x * blockDim.x + threadIdx.x;
    if (i < NTOK) g_rowsum[i] = 0.0f;
}

// split concat(u,z) -> g_Shi/g_Slo  [8192][1024]
__global__ __launch_bounds__(256) void split_S_kernel(
    const float* __restrict__ u, const float* __restrict__ z)
{
    int idx4 = blockIdx.x * 256 + threadIdx.x;       // float4 group
    int row = idx4 >> 8;                              // 256 groups/row
    int c = (idx4 & 255) * 4;
    const float* src = (c < 512) ? (u + (size_t)row * 512 + c) : (z + (size_t)row * 512 + c - 512);
    float4 v = *(const float4*)src;
    float x[4] = {v.x, v.y, v.z, v.w};
    bf16 h[4], l[4];
#pragma unroll
    for (int i = 0; i < 4; i++) split2(x[i], h[i], l[i]);
    size_t o = (size_t)row * INDIM + c;
    *(uint2*)(g_Shi + o) = make_uint2(packbf(h[0], h[1]), packbf(h[2], h[3]));
    *(uint2*)(g_Slo + o) = make_uint2(packbf(l[0], l[1]), packbf(l[2], l[3]));
}

// split W[512][1024] -> g_Whi[sel]/g_Wlo[sel]
__global__ __launch_bounds__(256) void split_W_kernel(const float* __restrict__ W, int sel)
{
    int idx4 = blockIdx.x * 256 + threadIdx.x;
    size_t o = (size_t)idx4 * 4;
    float4 v = *(const float4*)(W + o);
    float x[4] = {v.x, v.y, v.z, v.w};
    bf16 h[4], l[4];
#pragma unroll
    for (int i = 0; i < 4; i++) split2(x[i], h[i], l[i]);
    *(uint2*)(g_Whi[sel] + o) = make_uint2(packbf(h[0], h[1]), packbf(h[2], h[3]));
    *(uint2*)(g_Wlo[sel] + o) = make_uint2(packbf(l[0], l[1]), packbf(l[2], l[3]));
}

// ---------------------------------------------------------------------------
// Projection: tile 128x128, K=1024. sel: 0->K, 1->V(transposed), 2->Q
__global__ __launch_bounds__(256, 2) void proj_k(const float* __restrict__ bias, int sel)
{
    GEMM_PROLOG;
    const int row0 = blockIdx.y * 128, col0 = blockIdx.x * 128;
    GEMM_MAINLOOP(g_Shi, g_Slo, INDIM, row0, g_Whi[sel], g_Wlo[sel], INDIM, col0, INDIM / 32);

    bf16* ohi = (sel == 2) ? g_Qhi : g_Khi;
    bf16* olo = (sel == 2) ? g_Qlo : g_Klo;
#pragma unroll
    for (int i = 0; i < 4; i++)
#pragma unroll
        for (int hb = 0; hb < 2; hb++) {
            int grow = row0 + wm * 64 + i * 16 + (lane >> 2) + hb * 8;
#pragma unroll
            for (int j = 0; j < 4; j++) {
                int gcol = col0 + wn * 32 + j * 8 + (lane & 3) * 2;
                float v0 = acc[i][j][hb * 2]     + __ldg(bias + gcol);
                float v1 = acc[i][j][hb * 2 + 1] + __ldg(bias + gcol + 1);
                bf16 h0, l0, h1, l1;
                split2(v0, h0, l0); split2(v1, h1, l1);
                if (sel == 1) {
                    g_Vthi[(size_t)gcol * NTOK + grow] = h0;
                    g_Vtlo[(size_t)gcol * NTOK + grow] = l0;
                    g_Vthi[(size_t)(gcol + 1) * NTOK + grow] = h1;
                    g_Vtlo[(size_t)(gcol + 1) * NTOK + grow] = l1;
                } else {
                    size_t o = (size_t)grow * CDIM + gcol;
                    *(uint32_t*)(ohi + o) = packbf(h0, h1);
                    *(uint32_t*)(olo + o) = packbf(l0, l1);
                }
            }
        }
}

// ---------------------------------------------------------------------------
// Scores: P = exp(QK^T/sqrt(512)) unnormalized, diag=0, hi/lo bf16; rowsum.
__global__ __launch_bounds__(256, 2) void scores_k()
{
    GEMM_PROLOG;
    const int row0 = blockIdx.y * 128, col0 = blockIdx.x * 128;
    float* s_rsum = (float*)(smem + SM_RSUM);
    if (tid < 128) s_rsum[tid] = 0.0f;

    GEMM_MAINLOOP(g_Qhi, g_Qlo, CDIM, row0, g_Khi, g_Klo, CDIM, col0, CDIM / 32);

    const float scale = 0.044194173824159216f;  // 1/sqrt(512)
#pragma unroll
    for (int i = 0; i < 4; i++)
#pragma unroll
        for (int hb = 0; hb < 2; hb++) {
            int rloc = wm * 64 + i * 16 + (lane >> 2) + hb * 8;
            int grow = row0 + rloc;
            float part = 0.0f;
#pragma unroll
            for (int j = 0; j < 4; j++) {
                int gcol = col0 + wn * 32 + j * 8 + (lane & 3) * 2;
                float p0 = (grow == gcol)     ? 0.0f : __expf(acc[i][j][hb * 2]     * scale);
                float p1 = (grow == gcol + 1) ? 0.0f : __expf(acc[i][j][hb * 2 + 1] * scale);
                part += p0 + p1;
                bf16 h0, l0, h1, l1;
                split2(p0, h0, l0); split2(p1, h1, l1);
                size_t o = (size_t)grow * NTOK + gcol;
                *(uint32_t*)(g_Phi + o) = packbf(h0, h1);
                *(uint32_t*)(g_Plo + o) = packbf(l0, l1);
            }
            part += __shfl_xor_sync(0xFFFFFFFF, part, 1);
            part += __shfl_xor_sync(0xFFFFFFFF, part, 2);
            if ((lane & 3) == 0) atomicAdd(&s_rsum[rloc], part);
        }
    __syncthreads();
    if (tid < 128) atomicAdd(&g_rowsum[row0 + tid], s_rsum[tid]);
}

// ---------------------------------------------------------------------------
// AV: m_bar = (P_unnorm @ V) / rowsum.  Tile 128x128, K=8192.
__global__ __launch_bounds__(256, 2) void av_k(float* __restrict__ m_out)
{
    GEMM_PROLOG;
    const int row0 = blockIdx.y * 128, col0 = blockIdx.x * 128;
    GEMM_MAINLOOP(g_Phi, g_Plo, NTOK, row0, g_Vthi, g_Vtlo, NTOK, col0, NTOK / 32);

#pragma unroll
    for (int i = 0; i < 4; i++)
#pragma unroll
        for (int hb = 0; hb < 2; hb++) {
            int grow = row0 + wm * 64 + i * 16 + (lane >> 2) + hb * 8;
            float inv = 1.0f / __ldg(&g_rowsum[grow]);
#pragma unroll
            for (int j = 0; j < 4; j++) {
                int gcol = col0 + wn * 32 + j * 8 + (lane & 3) * 2;
                float2 o;
                o.x = acc[i][j][hb * 2]     * inv;
                o.y = acc[i][j][hb * 2 + 1] * inv;
                *(float2*)(m_out + (size_t)grow * CDIM + gcol) = o;
            }
        }
}

// ---------------------------------------------------------------------------
// attn[i,j] = (Phi+Plo)/rowsum[i]  (fp32 output)
__global__ __launch_bounds__(256) void normalize_k(float* __restrict__ attn)
{
    int64_t f8 = (int64_t)blockIdx.x * 256 + threadIdx.x;
    int row = (int)(f8 >> 10);
    int c0 = (int)((f8 & 1023) << 3);
    float inv = 1.0f / __ldg(&g_rowsum[row]);
    size_t base = (size_t)row * NTOK + c0;
    uint4 vh = *(const uint4*)(g_Phi + base);
    uint4 vl = *(const uint4*)(g_Plo + base);
    uint32_t hs[4] = {vh.x, vh.y, vh.z, vh.w};
    uint32_t ls[4] = {vl.x, vl.y, vl.z, vl.w};
    float o[8];
#pragma unroll
    for (int i = 0; i < 4; i++) {
        __nv_bfloat162 h2 = *reinterpret_cast<__nv_bfloat162*>(&hs[i]);
        __nv_bfloat162 l2 = *reinterpret_cast<__nv_bfloat162*>(&ls[i]);
        float2 hf = __bfloat1622float2(h2);
        float2 lf = __bfloat1622float2(l2);
        o[2 * i]     = (hf.x + lf.x) * inv;
        o[2 * i + 1] = (hf.y + lf.y) * inv;
    }
    *(float4*)(attn + base)     = make_float4(o[0], o[1], o[2], o[3]);
    *(float4*)(attn + base + 4) = make_float4(o[4], o[5], o[6], o[7]);
}

// ---------------------------------------------------------------------------
extern "C" void kernel_launch(void* const* d_in, const int* in_sizes, int n_in,
                              void* d_out, int out_size)
{
    (void)in_sizes; (void)n_in; (void)out_size;
    const float* u  = (const float*)d_in[0];
    const float* z  = (const float*)d_in[1];
    const float* Wk = (const float*)d_in[2];
    const float* bk = (const float*)d_in[3];
    const float* Wv = (const float*)d_in[4];
    const float* bv = (const float*)d_in[5];
    const float* Wq = (const float*)d_in[6];
    const float* bq = (const float*)d_in[7];

    float* m_out    = (float*)d_out;                  // (8192, 512)
    float* attn_out = m_out + (size_t)NTOK * CDIM;    // (8192, 8192)

    cudaFuncSetAttribute(proj_k,   cudaFuncAttributeMaxDynamicSharedMemorySize, SM_TOTAL);
    cudaFuncSetAttribute(scores_k, cudaFuncAttributeMaxDynamicSharedMemorySize, SM_TOTAL);
    cudaFuncSetAttribute(av_k,     cudaFuncAttributeMaxDynamicSharedMemorySize, SM_TOTAL);

    zero_rowsum_kernel<<<NTOK / 256, 256>>>();
    split_S_kernel<<<(NTOK * INDIM / 4) / 256, 256>>>(u, z);
    split_W_kernel<<<(CDIM * INDIM / 4) / 256, 256>>>(Wk, 0);
    split_W_kernel<<<(CDIM * INDIM / 4) / 256, 256>>>(Wv, 1);
    split_W_kernel<<<(CDIM * INDIM / 4) / 256, 256>>>(Wq, 2);

    dim3 pgrid(CDIM / 128, NTOK / 128);               // (4, 64)
    proj_k<<<pgrid, 256, SM_TOTAL>>>(bk, 0);
    proj_k<<<pgrid, 256, SM_TOTAL>>>(bv, 1);
    proj_k<<<pgrid, 256, SM_TOTAL>>>(bq, 2);

    dim3 sgrid(NTOK / 128, NTOK / 128);               // (64, 64)
    scores_k<<<sgrid, 256, SM_TOTAL>>>();

    dim3 agrid(CDIM / 128, NTOK / 128);               // (4, 64)
    av_k<<<agrid, 256, SM_TOTAL>>>(m_out);

    normalize_k<<<((size_t)NTOK * NTOK / 8) / 256, 256>>>(attn_out);
}

// round 5
// speedup vs baseline: 3.2458x; 1.3431x over previous
#include <cuda_runtime.h>
#include <cuda_bf16.h>
#include <cstdint>

#define NTOK  8192
#define INDIM 1024
#define CDIM  512

using bf16 = __nv_bfloat16;

// Packed tile format: 128 rows x 32 cols bf16, row pitch 80 B (64 data + 16 pad),
// hi half (10240 B) then lo half (10240 B) => 20480 B per tile, contiguous.
#define TILE_B  20480
#define TILE_HI 10240

// ---------------------------------------------------------------------------
// Scratch (__device__ globals; allocation-free rule). All tile-packed.
__device__ __align__(1024) char g_Sp[(size_t)2048 * TILE_B];        // S=concat(u,z): [rb 64][kc 32]
__device__ __align__(1024) char g_Wp[3][(size_t)128 * TILE_B];      // W: [rb 4][kc 32]
__device__ __align__(1024) char g_Qp[(size_t)1024 * TILE_B];        // Q: [rb 64][kc 16]
__device__ __align__(1024) char g_Kp[(size_t)1024 * TILE_B];        // K: [rb 64][kc 16]
__device__ __align__(1024) char g_Vtp[(size_t)1024 * TILE_B];       // V^T: [rb 4][kc 256]
__device__ __align__(1024) char g_Pp[(size_t)16384 * TILE_B];       // P: [rb 64][kc 256]
__device__ float g_rowsum[NTOK];

// ---------------------------------------------------------------------------
__device__ __forceinline__ uint32_t su32(const void* p) {
    uint32_t a;
    asm("{ .reg .u64 t; cvta.to.shared.u64 t, %1; cvt.u32.u64 %0, t; }" : "=r"(a) : "l"(p));
    return a;
}
__device__ __forceinline__ void mbar_init(uint32_t m, uint32_t c) {
    asm volatile("mbarrier.init.shared.b64 [%0], %1;" :: "r"(m), "r"(c) : "memory");
}
__device__ __forceinline__ void mbar_expect(uint32_t m, uint32_t bytes) {
    asm volatile("mbarrier.arrive.expect_tx.shared.b64 _, [%0], %1;" :: "r"(m), "r"(bytes) : "memory");
}
__device__ __forceinline__ void mbar_wait(uint32_t m, uint32_t parity) {
    asm volatile(
        "{\n\t.reg .pred P1;\n\t"
        "WL_%=:\n\t"
        "mbarrier.try_wait.parity.acquire.cta.shared::cta.b64 P1, [%0], %1, 0x989680;\n\t"
        "@P1 bra.uni WD_%=;\n\t"
        "bra.uni WL_%=;\n\t"
        "WD_%=:\n\t}"
        :: "r"(m), "r"(parity) : "memory");
}
__device__ __forceinline__ void bulk_g2s(uint32_t sdst, const void* gsrc, uint32_t bytes, uint32_t mbar) {
    asm volatile(
        "cp.async.bulk.shared::cluster.global.mbarrier::complete_tx::bytes [%0], [%1], %2, [%3];"
        :: "r"(sdst), "l"(__cvta_generic_to_global(gsrc)), "r"(bytes), "r"(mbar) : "memory");
}
__device__ __forceinline__ void ldm4(uint32_t& r0, uint32_t& r1, uint32_t& r2, uint32_t& r3, uint32_t a) {
    asm volatile("ldmatrix.sync.aligned.m8n8.x4.shared.b16 {%0,%1,%2,%3}, [%4];"
                 : "=r"(r0), "=r"(r1), "=r"(r2), "=r"(r3) : "r"(a));
}
__device__ __forceinline__ void mma16816(float* c, const uint32_t* a, const uint32_t* b) {
    asm volatile(
        "mma.sync.aligned.m16n8k16.row.col.f32.bf16.bf16.f32 "
        "{%0,%1,%2,%3}, {%4,%5,%6,%7}, {%8,%9}, {%0,%1,%2,%3};"
        : "+f"(c[0]), "+f"(c[1]), "+f"(c[2]), "+f"(c[3])
        : "r"(a[0]), "r"(a[1]), "r"(a[2]), "r"(a[3]), "r"(b[0]), "r"(b[1]));
}
__device__ __forceinline__ void split2(float v, bf16& h, bf16& l) {
    h = __float2bfloat16(v);
    l = __float2bfloat16(v - __bfloat162float(h));
}
__device__ __forceinline__ uint32_t packbf(bf16 a, bf16 b) {
    return ((uint32_t)__bfloat16_as_ushort(b) << 16) | __bfloat16_as_ushort(a);
}

// ---------------------------------------------------------------------------
// SMEM: stage = [A_HI 10240][A_LO 10240][B_HI 10240][B_LO 10240] = 40960 B; x2 stages
#define A_HI   0
#define A_LO   10240
#define B_HI   20480
#define B_LO   30720
#define STAGE  40960
#define SM_RSUM 81920
#define SM_MBAR 82432
#define SM_TOTAL 82448

// Compute one 32-K chunk, 3 split combos, into acc[4][4][4]. (Unchanged from R4.)
__device__ __forceinline__ void compute_stage(uint32_t sb, int wm, int wn, int lane,
                                              float acc[4][4][4])
{
    const uint32_t a_off = (lane & 15) * 80 + (lane >> 4) * 16;
    const uint32_t b_off = ((lane & 7) + ((lane >> 4) & 1) * 8) * 80 + ((lane >> 3) & 1) * 16;
#pragma unroll
    for (int kk = 0; kk < 2; kk++) {
        uint32_t bh[8], bl[8], a[16];
#pragma unroll
        for (int jj = 0; jj < 2; jj++) {
            uint32_t ad = sb + B_HI + (wn * 32 + jj * 16) * 80 + kk * 32 + b_off;
            ldm4(bh[jj * 4], bh[jj * 4 + 1], bh[jj * 4 + 2], bh[jj * 4 + 3], ad);
            ldm4(bl[jj * 4], bl[jj * 4 + 1], bl[jj * 4 + 2], bl[jj * 4 + 3], ad + (B_LO - B_HI));
        }
#pragma unroll
        for (int i = 0; i < 4; i++) {
            uint32_t ad = sb + A_HI + (wm * 64 + i * 16) * 80 + kk * 32 + a_off;
            ldm4(a[i * 4], a[i * 4 + 1], a[i * 4 + 2], a[i * 4 + 3], ad);
        }
#pragma unroll
        for (int i = 0; i < 4; i++)
#pragma unroll
            for (int j = 0; j < 4; j++) {
                mma16816(acc[i][j], &a[i * 4], &bh[j * 2]);
                mma16816(acc[i][j], &a[i * 4], &bl[j * 2]);
            }
#pragma unroll
        for (int i = 0; i < 4; i++) {
            uint32_t ad = sb + A_LO + (wm * 64 + i * 16) * 80 + kk * 32 + a_off;
            ldm4(a[i * 4], a[i * 4 + 1], a[i * 4 + 2], a[i * 4 + 3], ad);
        }
#pragma unroll
        for (int i = 0; i < 4; i++)
#pragma unroll
            for (int j = 0; j < 4; j++)
                mma16816(acc[i][j], &a[i * 4], &bh[j * 2]);
    }
}

// Double-buffered bulk-copy mainloop. One wait + one sync per chunk;
// loads are 2 cp.async.bulk per chunk, issued by thread 0.
#define PACKED_MAINLOOP(Abase, atile0, Bbase, btile0, NCH)                                   \
    if (tid == 0) { mbar_init(mb0, 1); mbar_init(mb1, 1); }                                  \
    __syncthreads();                                                                         \
    if (tid == 0) {                                                                          \
        mbar_expect(mb0, 2 * TILE_B);                                                        \
        bulk_g2s(sb,               (Abase) + (size_t)((atile0)) * TILE_B,       TILE_B, mb0);\
        bulk_g2s(sb + B_HI,        (Bbase) + (size_t)((btile0)) * TILE_B,       TILE_B, mb0);\
        mbar_expect(mb1, 2 * TILE_B);                                                        \
        bulk_g2s(sb + STAGE,       (Abase) + (size_t)((atile0) + 1) * TILE_B,   TILE_B, mb1);\
        bulk_g2s(sb + STAGE + B_HI,(Bbase) + (size_t)((btile0) + 1) * TILE_B,   TILE_B, mb1);\
    }                                                                                        \
    for (int kc = 0; kc < (NCH); kc++) {                                                     \
        uint32_t mb = (kc & 1) ? mb1 : mb0;                                                  \
        mbar_wait(mb, (kc >> 1) & 1);                                                        \
        compute_stage(sb + (kc & 1) * STAGE, wm, wn, lane, acc);                             \
        __syncthreads();                                                                     \
        if (tid == 0 && kc + 2 < (NCH)) {                                                    \
            mbar_expect(mb, 2 * TILE_B);                                                     \
            bulk_g2s(sb + (kc & 1) * STAGE,        (Abase) + (size_t)((atile0) + kc + 2) * TILE_B, TILE_B, mb); \
            bulk_g2s(sb + (kc & 1) * STAGE + B_HI, (Bbase) + (size_t)((btile0) + kc + 2) * TILE_B, TILE_B, mb); \
        }                                                                                    \
    }

#define GEMM_PROLOG                                                   \
    extern __shared__ char smem[];                                    \
    const uint32_t sb = su32(smem);                                   \
    const uint32_t mb0 = sb + SM_MBAR, mb1 = sb + SM_MBAR + 8;        \
    const int tid = threadIdx.x;                                      \
    const int lane = tid & 31, warp = tid >> 5;                       \
    const int wm = warp >> 2, wn = warp & 3;                          \
    float acc[4][4][4];                                               \
    _Pragma("unroll") for (int i = 0; i < 4; i++)                     \
    _Pragma("unroll") for (int j = 0; j < 4; j++)                     \
    _Pragma("unroll") for (int k = 0; k < 4; k++) acc[i][j][k] = 0.0f;

// ---------------------------------------------------------------------------
__global__ void zero_rowsum_kernel() {
    int i = blockIdx.x * blockDim.x + threadIdx.x;
    if (i < NTOK) g_rowsum[i] = 0.0f;
}

// split concat(u,z) fp32 -> packed hi/lo tiles in g_Sp
__global__ __launch_bounds__(256) void split_S_kernel(
    const float* __restrict__ u, const float* __restrict__ z)
{
    int idx = blockIdx.x * 256 + threadIdx.x;         // one 8-elem group
    int row = idx >> 7;                               // 128 groups per row
    int c0 = (idx & 127) * 8;
    const float* src = (c0 < 512) ? (u + (size_t)row * 512 + c0)
                                  : (z + (size_t)row * 512 + c0 - 512);
    float4 a = *(const float4*)src;
    float4 b = *(const float4*)(src + 4);
    float x[8] = {a.x, a.y, a.z, a.w, b.x, b.y, b.z, b.w};
    uint32_t hw[4], lw[4];
#pragma unroll
    for (int i = 0; i < 4; i++) {
        bf16 h0, l0, h1, l1;
        split2(x[2 * i], h0, l0); split2(x[2 * i + 1], h1, l1);
        hw[i] = packbf(h0, h1); lw[i] = packbf(l0, l1);
    }
    size_t t = (size_t)(row >> 7) * 32 + (c0 >> 5);
    size_t off = t * TILE_B + (size_t)(row & 127) * 80 + (c0 & 31) * 2;
    *(uint4*)(g_Sp + off)           = make_uint4(hw[0], hw[1], hw[2], hw[3]);
    *(uint4*)(g_Sp + off + TILE_HI) = make_uint4(lw[0], lw[1], lw[2], lw[3]);
}

// split W[512][1024] -> packed tiles in g_Wp[sel]
__global__ __launch_bounds__(256) void split_W_kernel(const float* __restrict__ W, int sel)
{
    int idx = blockIdx.x * 256 + threadIdx.x;
    int row = idx >> 7;
    int c0 = (idx & 127) * 8;
    const float* src = W + (size_t)row * INDIM + c0;
    float4 a = *(const float4*)src;
    float4 b = *(const float4*)(src + 4);
    float x[8] = {a.x, a.y, a.z, a.w, b.x, b.y, b.z, b.w};
    uint32_t hw[4], lw[4];
#pragma unroll
    for (int i = 0; i < 4; i++) {
        bf16 h0, l0, h1, l1;
        split2(x[2 * i], h0, l0); split2(x[2 * i + 1], h1, l1);
        hw[i] = packbf(h0, h1); lw[i] = packbf(l0, l1);
    }
    size_t t = (size_t)(row >> 7) * 32 + (c0 >> 5);
    size_t off = t * TILE_B + (size_t)(row & 127) * 80 + (c0 & 31) * 2;
    *(uint4*)(g_Wp[sel] + off)           = make_uint4(hw[0], hw[1], hw[2], hw[3]);
    *(uint4*)(g_Wp[sel] + off + TILE_HI) = make_uint4(lw[0], lw[1], lw[2], lw[3]);
}

// ---------------------------------------------------------------------------
// Projection: tile 128x128, K=1024. sel: 0->K, 1->V(transposed), 2->Q
__global__ __launch_bounds__(256, 2) void proj_k(const float* __restrict__ bias, int sel)
{
    GEMM_PROLOG;
    const int row0 = blockIdx.y * 128, col0 = blockIdx.x * 128;
    PACKED_MAINLOOP(g_Sp, (row0 >> 7) * 32, g_Wp[sel], (col0 >> 7) * 32, INDIM / 32);

    if (sel != 1) {
        char* outp = (sel == 2) ? g_Qp : g_Kp;
#pragma unroll
        for (int i = 0; i < 4; i++)
#pragma unroll
            for (int hb = 0; hb < 2; hb++) {
                int grow = row0 + wm * 64 + i * 16 + (lane >> 2) + hb * 8;
#pragma unroll
                for (int j = 0; j < 4; j++) {
                    int gcol = col0 + wn * 32 + j * 8 + (lane & 3) * 2;
                    float v0 = acc[i][j][hb * 2]     + __ldg(bias + gcol);
                    float v1 = acc[i][j][hb * 2 + 1] + __ldg(bias + gcol + 1);
                    bf16 h0, l0, h1, l1;
                    split2(v0, h0, l0); split2(v1, h1, l1);
                    size_t t = (size_t)(grow >> 7) * 16 + (gcol >> 5);
                    size_t off = t * TILE_B + (size_t)(grow & 127) * 80 + (gcol & 31) * 2;
                    *(uint32_t*)(outp + off)           = packbf(h0, h1);
                    *(uint32_t*)(outp + off + TILE_HI) = packbf(l0, l1);
                }
            }
    } else {
        // V: transpose via smem then packed 16B stores into g_Vtp
        // planes: hi at smem[0], lo at smem[34816]; pitch 272 B, [c 128][tok 128]
#pragma unroll
        for (int i = 0; i < 4; i++)
#pragma unroll
            for (int hb = 0; hb < 2; hb++) {
                int tok = wm * 64 + i * 16 + (lane >> 2) + hb * 8;      // local token
#pragma unroll
                for (int j = 0; j < 4; j++) {
                    int cl = wn * 32 + j * 8 + (lane & 3) * 2;          // local c
                    float v0 = acc[i][j][hb * 2]     + __ldg(bias + col0 + cl);
                    float v1 = acc[i][j][hb * 2 + 1] + __ldg(bias + col0 + cl + 1);
                    bf16 h0, l0, h1, l1;
                    split2(v0, h0, l0); split2(v1, h1, l1);
                    *(bf16*)(smem + cl * 272 + tok * 2)               = h0;
                    *(bf16*)(smem + 34816 + cl * 272 + tok * 2)       = l0;
                    *(bf16*)(smem + (cl + 1) * 272 + tok * 2)         = h1;
                    *(bf16*)(smem + 34816 + (cl + 1) * 272 + tok * 2) = l1;
                }
            }
        __syncthreads();
        for (int q = tid; q < 2048; q += 256) {
            int c = q >> 4, t8 = (q & 15) * 8;
            uint4 vh = *(uint4*)(smem + c * 272 + t8 * 2);
            uint4 vl = *(uint4*)(smem + 34816 + c * 272 + t8 * 2);
            size_t t = (size_t)(col0 >> 7) * 256 + ((row0 + t8) >> 5);
            size_t off = t * TILE_B + (size_t)c * 80 + (t8 & 31) * 2;
            *(uint4*)(g_Vtp + off)           = vh;
            *(uint4*)(g_Vtp + off + TILE_HI) = vl;
        }
    }
}

// ---------------------------------------------------------------------------
// Scores: P = exp(QK^T/sqrt(512)) unnormalized, diag=0, packed hi/lo; rowsum.
__global__ __launch_bounds__(256, 2) void scores_k()
{
    GEMM_PROLOG;
    const int row0 = blockIdx.y * 128, col0 = blockIdx.x * 128;
    float* s_rsum = (float*)(smem + SM_RSUM);
    if (tid < 128) s_rsum[tid] = 0.0f;

    PACKED_MAINLOOP(g_Qp, (row0 >> 7) * 16, g_Kp, (col0 >> 7) * 16, CDIM / 32);

    const float scale = 0.044194173824159216f;  // 1/sqrt(512)
#pragma unroll
    for (int i = 0; i < 4; i++)
#pragma unroll
        for (int hb = 0; hb < 2; hb++) {
            int rloc = wm * 64 + i * 16 + (lane >> 2) + hb * 8;
            int grow = row0 + rloc;
            float part = 0.0f;
#pragma unroll
            for (int j = 0; j < 4; j++) {
                int gcol = col0 + wn * 32 + j * 8 + (lane & 3) * 2;
                float p0 = (grow == gcol)     ? 0.0f : __expf(acc[i][j][hb * 2]     * scale);
                float p1 = (grow == gcol + 1) ? 0.0f : __expf(acc[i][j][hb * 2 + 1] * scale);
                part += p0 + p1;
                bf16 h0, l0, h1, l1;
                split2(p0, h0, l0); split2(p1, h1, l1);
                size_t t = (size_t)(grow >> 7) * 256 + (gcol >> 5);
                size_t off = t * TILE_B + (size_t)(grow & 127) * 80 + (gcol & 31) * 2;
                *(uint32_t*)(g_Pp + off)           = packbf(h0, h1);
                *(uint32_t*)(g_Pp + off + TILE_HI) = packbf(l0, l1);
            }
            part += __shfl_xor_sync(0xFFFFFFFF, part, 1);
            part += __shfl_xor_sync(0xFFFFFFFF, part, 2);
            if ((lane & 3) == 0) atomicAdd(&s_rsum[rloc], part);
        }
    __syncthreads();
    if (tid < 128) atomicAdd(&g_rowsum[row0 + tid], s_rsum[tid]);
}

// ---------------------------------------------------------------------------
// AV: m_bar = (P_unnorm @ V) / rowsum.  Tile 128x128, K=8192.
__global__ __launch_bounds__(256, 2) void av_k(float* __restrict__ m_out)
{
    GEMM_PROLOG;
    const int row0 = blockIdx.y * 128, col0 = blockIdx.x * 128;
    PACKED_MAINLOOP(g_Pp, (row0 >> 7) * 256, g_Vtp, (col0 >> 7) * 256, NTOK / 32);

#pragma unroll
    for (int i = 0; i < 4; i++)
#pragma unroll
        for (int hb = 0; hb < 2; hb++) {
            int grow = row0 + wm * 64 + i * 16 + (lane >> 2) + hb * 8;
            float inv = 1.0f / __ldg(&g_rowsum[grow]);
#pragma unroll
            for (int j = 0; j < 4; j++) {
                int gcol = col0 + wn * 32 + j * 8 + (lane & 3) * 2;
                float2 o;
                o.x = acc[i][j][hb * 2]     * inv;
                o.y = acc[i][j][hb * 2 + 1] * inv;
                *(float2*)(m_out + (size_t)grow * CDIM + gcol) = o;
            }
        }
}

// ---------------------------------------------------------------------------
// attn[i,j] = (Phi+Plo)/rowsum[i], reading packed P, writing row-major fp32.
__global__ __launch_bounds__(256) void normalize_k(float* __restrict__ attn)
{
    int64_t q = (int64_t)blockIdx.x * 256 + threadIdx.x;   // one 8-elem group
    int i = (int)(q >> 10);                                // 1024 groups per row
    int w = (int)(q & 1023);
    int kc = w >> 2, cc8 = (w & 3) * 16;                   // byte offset of 16B chunk
    float inv = 1.0f / __ldg(&g_rowsum[i]);
    size_t t = (size_t)(i >> 7) * 256 + kc;
    size_t off = t * TILE_B + (size_t)(i & 127) * 80 + cc8;
    uint4 vh = *(const uint4*)(g_Pp + off);
    uint4 vl = *(const uint4*)(g_Pp + off + TILE_HI);
    uint32_t hs[4] = {vh.x, vh.y, vh.z, vh.w};
    uint32_t ls[4] = {vl.x, vl.y, vl.z, vl.w};
    float o[8];
#pragma unroll
    for (int k = 0; k < 4; k++) {
        __nv_bfloat162 h2 = *reinterpret_cast<__nv_bfloat162*>(&hs[k]);
        __nv_bfloat162 l2 = *reinterpret_cast<__nv_bfloat162*>(&ls[k]);
        float2 hf = __bfloat1622float2(h2);
        float2 lf = __bfloat1622float2(l2);
        o[2 * k]     = (hf.x + lf.x) * inv;
        o[2 * k + 1] = (hf.y + lf.y) * inv;
    }
    float* dst = attn + (size_t)i * NTOK + kc * 32 + (cc8 >> 1);
    *(float4*)(dst)     = make_float4(o[0], o[1], o[2], o[3]);
    *(float4*)(dst + 4) = make_float4(o[4], o[5], o[6], o[7]);
}

// ---------------------------------------------------------------------------
extern "C" void kernel_launch(void* const* d_in, const int* in_sizes, int n_in,
                              void* d_out, int out_size)
{
    (void)in_sizes; (void)n_in; (void)out_size;
    const float* u  = (const float*)d_in[0];
    const float* z  = (const float*)d_in[1];
    const float* Wk = (const float*)d_in[2];
    const float* bk = (const float*)d_in[3];
    const float* Wv = (const float*)d_in[4];
    const float* bv = (const float*)d_in[5];
    const float* Wq = (const float*)d_in[6];
    const float* bq = (const float*)d_in[7];

    float* m_out    = (float*)d_out;                  // (8192, 512)
    float* attn_out = m_out + (size_t)NTOK * CDIM;    // (8192, 8192)

    cudaFuncSetAttribute(proj_k,   cudaFuncAttributeMaxDynamicSharedMemorySize, SM_TOTAL);
    cudaFuncSetAttribute(scores_k, cudaFuncAttributeMaxDynamicSharedMemorySize, SM_TOTAL);
    cudaFuncSetAttribute(av_k,     cudaFuncAttributeMaxDynamicSharedMemorySize, SM_TOTAL);

    zero_rowsum_kernel<<<NTOK / 256, 256>>>();
    split_S_kernel<<<(NTOK * INDIM / 8) / 256, 256>>>(u, z);
    split_W_kernel<<<(CDIM * INDIM / 8) / 256, 256>>>(Wk, 0);
    split_W_kernel<<<(CDIM * INDIM / 8) / 256, 256>>>(Wv, 1);
    split_W_kernel<<<(CDIM * INDIM / 8) / 256, 256>>>(Wq, 2);

    dim3 pgrid(CDIM / 128, NTOK / 128);               // (4, 64)
    proj_k<<<pgrid, 256, SM_TOTAL>>>(bk, 0);
    proj_k<<<pgrid, 256, SM_TOTAL>>>(bv, 1);
    proj_k<<<pgrid, 256, SM_TOTAL>>>(bq, 2);

    dim3 sgrid(NTOK / 128, NTOK / 128);               // (64, 64)
    scores_k<<<sgrid, 256, SM_TOTAL>>>();

    dim3 agrid(CDIM / 128, NTOK / 128);               // (4, 64)
    av_k<<<agrid, 256, SM_TOTAL>>>(m_out);

    normalize_k<<<(unsigned)(((size_t)NTOK * NTOK / 8) / 256), 256>>>(attn_out);
}